// round 5
// baseline (speedup 1.0000x reference)
#include <cuda_runtime.h>

// B-spline layer: out[b,f] = sum_k N_k(x[b,f]) * cp[k,f] + bias[f]
// Cubic clamped uniform B-spline, K=64 -> interior spacing h = 1/61.
// Only 4 basis funcs nonzero per x; span m = floor(61*x) in [0,60].
// Knot-unit formulation: knots are small integers; 1/den for den in {1,2,3}
// via linear+clamp FMAs (exact at integer gaps) -- no MUFU RCP.
//
// R5: force ILP=4 structurally. Stage-split so all 4 chains are live:
//   stage A: 4x LDG (x values)
//   stage B: span m per j + issue all 16 control-point LDS immediately
//            (LDS latency hides under the basis math, not after it)
//   stage C: 4 independent basis chains
//   stage D: dots (operands already resident) + stores

#define NK 64
#define NF 128
#define U  4

__global__ __launch_bounds__(512, 2)
void bspline_kernel(const float* __restrict__ x,
                    const float* __restrict__ cp,
                    const float* __restrict__ bias,
                    float* __restrict__ out)
{
    __shared__ float cs[NK * NF];   // 32 KB control points [k][f]

    const int tid = threadIdx.x;

    // Cooperative fill: 8192 floats = 2048 float4 / 512 thr = 4 each
    {
        const float4* __restrict__ src = (const float4*)cp;
        float4* dst = (float4*)cs;
#pragma unroll
        for (int i = 0; i < (NK * NF / 4) / 512; i++)
            dst[tid + i * 512] = src[tid + i * 512];
    }

    const int f    = tid & (NF - 1);   // feature column (bank = lane -> conflict-free)
    const int lrow = tid >> 7;         // 0..3
    const float bf = __ldg(&bias[f]);

    __syncthreads();

    // Single shot: block handles rows [bid*16, bid*16+16); this thread does
    // rows base .. base+3.
    const int base = blockIdx.x * (4 * U) + lrow * U;

    // ---- stage A: batched global loads (MLP = 4) ----
    float xv[U];
#pragma unroll
    for (int j = 0; j < U; j++)
        xv[j] = x[(base + j) * NF + f];

    // ---- stage B: spans + early control-point gathers ----
    float u[U], fm[U];
    float c0[U], c1[U], c2[U], c3[U];
#pragma unroll
    for (int j = 0; j < U; j++) {
        u[j]  = xv[j] * 61.0f;
        fm[j] = floorf(u[j]);            // x in [0,1) -> m in [0,60]
        const int m = (int)fm[j];
        const float* __restrict__ c = &cs[m * NF + f];
        c0[j] = c[0 * NF];
        c1[j] = c[1 * NF];
        c2[j] = c[2 * NF];
        c3[j] = c[3 * NF];
    }

    // ---- stage C: 4 independent basis chains ----
    float N0[U], N1[U], N2[U], N3[U];
#pragma unroll
    for (int j = 0; j < U; j++) {
        const float uu = u[j], f0 = fm[j];

        const float km1 = fmaxf(f0 - 1.0f, 0.0f);
        const float km2 = fmaxf(f0 - 2.0f, 0.0f);
        const float k2  = fminf(f0 + 2.0f, 61.0f);
        const float k3  = fminf(f0 + 3.0f, 61.0f);

        const float l1 = uu - f0;
        const float r1 = f0 + 1.0f - uu;
        const float l2 = uu - km1;
        const float l3 = uu - km2;
        const float r2 = k2 - uu;
        const float r3 = k3 - uu;

        // reciprocal denominators: linear + clamp, exact at integer knot gaps
        const float lo  = fmaf(f0, -0.5f,   1.0f);
        const float hi  = fmaf(f0,  0.5f, -29.0f);
        const float i21 = fmaxf(0.5f,        lo);
        const float i22 = fmaxf(0.5f,        hi);
        const float i31 = fmaxf(0.33333334f, lo);
        const float i33 = fmaxf(0.33333334f, hi);
        const float i32 = fmaf(k2 - km1, -0.16666667f, 0.83333331f);

        // degree 1 -> 2
        float t = r1 * i21;
        float a = r1 * t;
        float s = l2 * t;
        t       = l1 * i22;
        float b = fmaf(r2, t, s);
        float c = l1 * t;

        // degree 2 -> 3
        t = a * i31;
        N0[j] = r1 * t;
        s     = l3 * t;
        t = b * i32;
        N1[j] = fmaf(r2, t, s);
        s     = l2 * t;
        t = c * i33;
        N2[j] = fmaf(r3, t, s);
        N3[j] = l1 * t;
    }

    // ---- stage D: dots (control points already resident) + stores ----
#pragma unroll
    for (int j = 0; j < U; j++) {
        float a = fmaf(N0[j], c0[j], bf);
        a = fmaf(N1[j], c1[j], a);
        a = fmaf(N2[j], c2[j], a);
        a = fmaf(N3[j], c3[j], a);
        out[(base + j) * NF + f] = a;
    }
}

extern "C" void kernel_launch(void* const* d_in, const int* in_sizes, int n_in,
                              void* d_out, int out_size)
{
    const float* x    = (const float*)d_in[0];
    const float* cp   = (const float*)d_in[1];
    const float* bias = (const float*)d_in[2];
    float* out = (float*)d_out;

    const int B = in_sizes[0] / NF;         // 16384 rows
    const int grid = B / (4 * U);           // 1024 blocks, one shot each

    bspline_kernel<<<grid, 512>>>(x, cp, bias, out);
}